// round 2
// baseline (speedup 1.0000x reference)
#include <cuda_runtime.h>
#include <math.h>

#define B_ 64
#define T_ 1024
#define I_ 128
#define H_ 512
#define O_ 128
#define GRID0 128
#define NT 256
#define FCT 256
#define KC 128
#define WST0 644
#define WST1 1028

typedef unsigned long long ull;

// ---- scratch (device globals: allocation-free) ----
__device__ float g_xT[T_ * I_ * B_];      // x transposed: [t][i][b]
__device__ float g_h0buf[2 * H_ * B_];    // layer0 h double buffer: [t&1][h][b]
__device__ float g_h1[T_ * H_ * B_];      // layer1 h history: [t][h][b]
__device__ unsigned g_bar_count;
__device__ unsigned g_bar_sense;

// ---- packed f32x2 helpers ----
__device__ __forceinline__ ull pack2(float x) {
    ull r; unsigned u = __float_as_uint(x);
    asm("mov.b64 %0, {%1, %1};" : "=l"(r) : "r"(u));
    return r;
}
__device__ __forceinline__ void ffma2(ull &acc, ull a, ull w) {
    asm("fma.rn.f32x2 %0, %1, %2, %0;" : "+l"(acc) : "l"(a), "l"(w));
}
__device__ __forceinline__ float lo2(ull v) { return __uint_as_float((unsigned)v); }
__device__ __forceinline__ float hi2(ull v) { return __uint_as_float((unsigned)(v >> 32)); }

__device__ __forceinline__ void cp16(float* dst, const float* src) {
    unsigned ds = (unsigned)__cvta_generic_to_shared(dst);
    asm volatile("cp.async.cg.shared.global [%0], [%1], 16;" :: "r"(ds), "l"(src));
}

// ---- sense-reversing grid barrier (state self-restoring: count returns to 0;
//      sense is re-read at kernel start so graph replays are safe) ----
__device__ __forceinline__ void gridbar(unsigned &sense) {
    __syncthreads();
    if (threadIdx.x == 0) {
        __threadfence();
        unsigned s = sense ^ 1u;
        sense = s;
        if (atomicAdd(&g_bar_count, 1u) == GRID0 - 1u) {
            g_bar_count = 0u;
            __threadfence();
            atomicExch(&g_bar_sense, s);
        } else {
            while (atomicAdd(&g_bar_sense, 0u) != s) { __nanosleep(64); }
        }
        __threadfence();
    }
    __syncthreads();
}

// ---------------------------------------------------------------------------
// x[b][t][i] -> g_xT[t][i][b]
__global__ void __launch_bounds__(NT) transpose_kernel(const float* __restrict__ x) {
    __shared__ float tile[B_][I_ + 1];
    int t = blockIdx.x;
    for (int idx = threadIdx.x; idx < B_ * I_; idx += NT) {
        int b = idx >> 7, i = idx & 127;
        tile[b][i] = x[(b * T_ + t) * I_ + i];
    }
    __syncthreads();
    for (int idx = threadIdx.x; idx < B_ * I_; idx += NT) {
        int b = idx & 63, i = idx >> 6;
        g_xT[t * I_ * B_ + i * B_ + b] = tile[b][i];
    }
}

// ---------------------------------------------------------------------------
// One LSTM step for this CTA's 4 h-columns (16 gate rows).
// Input vector (length KD) = concat(srcA[0:len0], srcB[...]) laid out [k][b];
// srcB==nullptr means zeros (t==0 state).
__device__ __forceinline__ void lstm_step(
    const float* __restrict__ Ws, const int WST, const int KD,
    const float* __restrict__ bias,
    float* __restrict__ ins,   // 2 * KC * 64 double buffer
    float* __restrict__ red,   // 4 * 16 * 64
    const float* __restrict__ srcA, const int len0,
    const float* __restrict__ srcB,
    float* __restrict__ hout, float &cst)
{
    const int tid = threadIdx.x;
    const int ks = tid >> 6;          // k-split group 0..3
    const int jp = (tid >> 3) & 7;    // row pair 0..7 -> rows 2jp, 2jp+1
    const int bo = tid & 7;           // batch octet

    ull acc[8];
#pragma unroll
    for (int i = 0; i < 8; i++) acc[i] = 0ull;

    const int nc = KD / KC;

    // prefetch chunk 0
    {
#pragma unroll
        for (int it = 0; it < 8; it++) {
            int v = tid + it * NT;
            int kk = v >> 4, c4 = (v & 15) << 2;
            float* dst = ins + v * 4;
            if (kk < len0)      cp16(dst, srcA + kk * B_ + c4);
            else if (srcB)      cp16(dst, srcB + (kk - len0) * B_ + c4);
            else                *(float4*)dst = make_float4(0.f, 0.f, 0.f, 0.f);
        }
        asm volatile("cp.async.commit_group;");
    }

    for (int c = 0; c < nc; c++) {
        if (c + 1 < nc) {
            int kb = (c + 1) * KC;
            float* buf = ins + ((c + 1) & 1) * (KC * B_);
#pragma unroll
            for (int it = 0; it < 8; it++) {
                int v = tid + it * NT;
                int kk = v >> 4, c4 = (v & 15) << 2;
                int kg = kb + kk;
                float* dst = buf + v * 4;
                if (kg < len0)      cp16(dst, srcA + kg * B_ + c4);
                else if (srcB)      cp16(dst, srcB + (kg - len0) * B_ + c4);
                else                *(float4*)dst = make_float4(0.f, 0.f, 0.f, 0.f);
            }
            asm volatile("cp.async.commit_group;");
            asm volatile("cp.async.wait_group 1;");
        } else {
            asm volatile("cp.async.wait_group 0;");
        }
        __syncthreads();

        const float* buf = ins + (c & 1) * (KC * B_);
        const float* w0p = Ws + (2 * jp) * WST + c * KC + ks * (KC / 4);
        const float* w1p = w0p + WST;
        const float* ap  = buf + ks * (KC / 4) * B_ + bo * 8;
#pragma unroll 8
        for (int kk = 0; kk < KC / 4; kk++) {
            ulonglong2 A0 = *(const ulonglong2*)(ap + kk * B_);
            ulonglong2 A1 = *(const ulonglong2*)(ap + kk * B_ + 4);
            ull w0 = pack2(w0p[kk]);
            ull w1 = pack2(w1p[kk]);
            ffma2(acc[0], A0.x, w0); ffma2(acc[1], A0.y, w0);
            ffma2(acc[2], A1.x, w0); ffma2(acc[3], A1.y, w0);
            ffma2(acc[4], A0.x, w1); ffma2(acc[5], A0.y, w1);
            ffma2(acc[6], A1.x, w1); ffma2(acc[7], A1.y, w1);
        }
        __syncthreads();
    }

    // k-split reduction through smem
    {
        int base = ks * 1024 + (2 * jp) * B_ + bo * 8;
        *(ull*)(red + base + 0) = acc[0];
        *(ull*)(red + base + 2) = acc[1];
        *(ull*)(red + base + 4) = acc[2];
        *(ull*)(red + base + 6) = acc[3];
        base += B_;
        *(ull*)(red + base + 0) = acc[4];
        *(ull*)(red + base + 2) = acc[5];
        *(ull*)(red + base + 4) = acc[6];
        *(ull*)(red + base + 6) = acc[7];
    }
    __syncthreads();

    // activations: thread owns (local col c4, batch b)
    {
        int c4 = tid >> 6;
        int b  = tid & 63;
        float xi = bias[c4], xf = bias[4 + c4], xg = bias[8 + c4], xo = bias[12 + c4];
#pragma unroll
        for (int s = 0; s < 4; s++) {
            const float* r = red + s * 1024 + b;
            xi += r[(0 + c4) * B_];
            xf += r[(4 + c4) * B_];
            xg += r[(8 + c4) * B_];
            xo += r[(12 + c4) * B_];
        }
        float ii = 1.f / (1.f + expf(-xi));
        float ff = 1.f / (1.f + expf(-xf));
        float gg = tanhf(xg);
        float oo = 1.f / (1.f + expf(-xo));
        cst = ff * cst + ii * gg;
        hout[c4 * B_ + b] = oo * tanhf(cst);
    }
}

// ---------------------------------------------------------------------------
// Persistent kernel: both LSTM layers, pipelined one step apart.
__global__ void __launch_bounds__(NT, 1) lstm_kernel(
    const float* __restrict__ W_ih0, const float* __restrict__ W_hh0,
    const float* __restrict__ b_ih0, const float* __restrict__ b_hh0,
    const float* __restrict__ W_ih1, const float* __restrict__ W_hh1,
    const float* __restrict__ b_ih1, const float* __restrict__ b_hh1)
{
    extern __shared__ float sm[];
    float* Ws0   = sm;                      // 16 * 644
    float* Ws1   = Ws0 + 16 * WST0;         // 16 * 1028
    float* bias0 = Ws1 + 16 * WST1;         // 16
    float* bias1 = bias0 + 16;              // 16
    float* ins   = bias1 + 16;              // 2 * KC * 64
    float* red   = ins + 2 * KC * B_;       // 4 * 16 * 64

    const int tid = threadIdx.x;
    const int hj0 = blockIdx.x * 4;

    // load weight slices: local row r = gate*4 + c  <->  global row gate*512 + hj0 + c
    for (int idx = tid; idx < 16 * 640; idx += NT) {
        int r = idx / 640, k = idx - r * 640;
        int grow = (r >> 2) * H_ + hj0 + (r & 3);
        Ws0[r * WST0 + k] = (k < I_) ? W_ih0[grow * I_ + k]
                                     : W_hh0[grow * H_ + (k - I_)];
    }
    for (int idx = tid; idx < 16 * 1024; idx += NT) {
        int r = idx >> 10, k = idx & 1023;
        int grow = (r >> 2) * H_ + hj0 + (r & 3);
        Ws1[r * WST1 + k] = (k < H_) ? W_ih1[grow * H_ + k]
                                     : W_hh1[grow * H_ + (k - H_)];
    }
    if (tid < 16) {
        int grow = (tid >> 2) * H_ + hj0 + (tid & 3);
        bias0[tid] = b_ih0[grow] + b_hh0[grow];
        bias1[tid] = b_ih1[grow] + b_hh1[grow];
    }

    unsigned sense = 0;
    if (tid == 0) sense = atomicAdd(&g_bar_sense, 0u);

    float c0st = 0.f, c1st = 0.f;
    __syncthreads();

    for (int k = 0; k < T_ + 1; ++k) {
        if (k < T_) {   // layer0 at t = k : input [x_t ; h0[t-1]]
            int t = k;
            const float* srcB = (t > 0) ? (g_h0buf + ((t - 1) & 1) * H_ * B_) : (const float*)0;
            float* hout = g_h0buf + (t & 1) * H_ * B_ + hj0 * B_;
            lstm_step(Ws0, WST0, 640, bias0, ins, red,
                      g_xT + t * I_ * B_, I_, srcB, hout, c0st);
        }
        if (k >= 1) {   // layer1 at s = k-1 : input [h0[s] ; h1[s-1]]
            int s = k - 1;
            const float* srcB = (s > 0) ? (g_h1 + (s - 1) * H_ * B_) : (const float*)0;
            float* hout = g_h1 + s * H_ * B_ + hj0 * B_;
            lstm_step(Ws1, WST1, 1024, bias1, ins, red,
                      g_h0buf + (s & 1) * H_ * B_, H_, srcB, hout, c1st);
        }
        gridbar(sense);
    }
}

// ---------------------------------------------------------------------------
// FC: out[b][t][o] = sum_h h1[t][h][b] * Wfc[o][h] + bfc[o]. One CTA per t.
__global__ void __launch_bounds__(FCT) fc_kernel(
    const float* __restrict__ Wfc, const float* __restrict__ bfc,
    float* __restrict__ out)
{
    extern __shared__ float sm[];
    float* w_s = sm;                  // 128 x 65
    float* h_s = w_s + O_ * 65;       // 64 x 64
    float* o_s = h_s + 64 * B_;       // 64 x 128

    int t = blockIdx.x;
    int tid = threadIdx.x;
    int ot = tid & 15;                // o = ot + j*16
    int bt = tid >> 4;                // b = bt*4 .. bt*4+3

    ull acc[16];
#pragma unroll
    for (int i = 0; i < 16; i++) acc[i] = 0ull;

    for (int kb = 0; kb < H_; kb += 64) {
        __syncthreads();
        for (int idx = tid; idx < O_ * 64; idx += FCT) {
            int o = idx >> 6, kk = idx & 63;
            w_s[o * 65 + kk] = Wfc[o * H_ + kb + kk];
        }
        for (int idx = tid; idx < 64 * B_; idx += FCT) {
            h_s[idx] = g_h1[(t * H_ + kb) * B_ + idx];
        }
        __syncthreads();
#pragma unroll 4
        for (int kk = 0; kk < 64; kk++) {
            ulonglong2 A = *(const ulonglong2*)(h_s + kk * B_ + bt * 4);
#pragma unroll
            for (int j = 0; j < 8; j++) {
                ull w = pack2(w_s[(ot + j * 16) * 65 + kk]);
                ffma2(acc[j * 2 + 0], A.x, w);
                ffma2(acc[j * 2 + 1], A.y, w);
            }
        }
    }
    __syncthreads();
#pragma unroll
    for (int j = 0; j < 8; j++) {
        int o = ot + j * 16;
        o_s[(bt * 4 + 0) * O_ + o] = lo2(acc[j * 2 + 0]);
        o_s[(bt * 4 + 1) * O_ + o] = hi2(acc[j * 2 + 0]);
        o_s[(bt * 4 + 2) * O_ + o] = lo2(acc[j * 2 + 1]);
        o_s[(bt * 4 + 3) * O_ + o] = hi2(acc[j * 2 + 1]);
    }
    __syncthreads();
    for (int idx = tid; idx < B_ * O_; idx += FCT) {
        int b = idx >> 7, o = idx & 127;
        out[(b * T_ + t) * O_ + o] = o_s[idx] + bfc[o];
    }
}

// ---------------------------------------------------------------------------
extern "C" void kernel_launch(void* const* d_in, const int* in_sizes, int n_in,
                              void* d_out, int out_size) {
    const float* x     = (const float*)d_in[0];
    const float* W_ih0 = (const float*)d_in[1];
    const float* W_hh0 = (const float*)d_in[2];
    const float* b_ih0 = (const float*)d_in[3];
    const float* b_hh0 = (const float*)d_in[4];
    const float* W_ih1 = (const float*)d_in[5];
    const float* W_hh1 = (const float*)d_in[6];
    const float* b_ih1 = (const float*)d_in[7];
    const float* b_hh1 = (const float*)d_in[8];
    const float* W_fc  = (const float*)d_in[9];
    const float* b_fc  = (const float*)d_in[10];
    float* out = (float*)d_out;

    size_t smem_lstm = (size_t)(16 * WST0 + 16 * WST1 + 32 + 2 * KC * B_ + 4 * 16 * B_) * sizeof(float);
    size_t smem_fc   = (size_t)(O_ * 65 + 64 * B_ + B_ * O_) * sizeof(float);

    cudaFuncSetAttribute(lstm_kernel, cudaFuncAttributeMaxDynamicSharedMemorySize, (int)smem_lstm);
    cudaFuncSetAttribute(fc_kernel,   cudaFuncAttributeMaxDynamicSharedMemorySize, (int)smem_fc);

    transpose_kernel<<<T_, NT>>>(x);
    lstm_kernel<<<GRID0, NT, smem_lstm>>>(W_ih0, W_hh0, b_ih0, b_hh0,
                                          W_ih1, W_hh1, b_ih1, b_hh1);
    fc_kernel<<<T_, FCT, smem_fc>>>(W_fc, b_fc, out);
}